// round 10
// baseline (speedup 1.0000x reference)
#include <cuda_runtime.h>
#include <cuda_fp16.h>
#include <cstdint>

#define NHEADS 8
#define EMBED  512
#define HD     64
#define BATCH  4
#define SEQ    2048
#define STR    72   // smem tile stride in halves (144B rows)

// ---- scratch (allocation-free: __device__ globals) ----
__device__ __half g_Qh[BATCH*NHEADS*SEQ*HD];   // pre-scaled by log2(e)/sqrt(512)
__device__ __half g_Kh[BATCH*NHEADS*SEQ*HD];
__device__ __half g_Vh[BATCH*NHEADS*SEQ*HD];
__device__ __half g_Oh[BATCH*SEQ*EMBED];       // attention output pre-Wo (fp16)
__device__ __half g_Ps[BATCH*NHEADS*SEQ*SEQ];  // unnormalized exp(P) scratch (268MB)

__device__ __forceinline__ uint32_t saddr(const void* p){
    return (uint32_t)__cvta_generic_to_shared(p);
}
__device__ __forceinline__ void cp16(uint32_t d, const void* s){
    asm volatile("cp.async.cg.shared.global [%0], [%1], 16;\n" :: "r"(d), "l"(s));
}
#define CP_COMMIT() asm volatile("cp.async.commit_group;\n")
#define CP_WAIT0()  asm volatile("cp.async.wait_group 0;\n")

__device__ __forceinline__ void ldsm4(uint32_t* r, uint32_t a){
    asm volatile("ldmatrix.sync.aligned.m8n8.x4.shared.b16 {%0,%1,%2,%3}, [%4];\n"
        : "=r"(r[0]),"=r"(r[1]),"=r"(r[2]),"=r"(r[3]) : "r"(a));
}
__device__ __forceinline__ void ldsm4t(uint32_t* r, uint32_t a){
    asm volatile("ldmatrix.sync.aligned.m8n8.x4.trans.shared.b16 {%0,%1,%2,%3}, [%4];\n"
        : "=r"(r[0]),"=r"(r[1]),"=r"(r[2]),"=r"(r[3]) : "r"(a));
}
__device__ __forceinline__ void mma16(float* c, const uint32_t* a, const uint32_t* b){
    asm volatile(
        "mma.sync.aligned.m16n8k16.row.col.f32.f16.f16.f32 "
        "{%0,%1,%2,%3}, {%4,%5,%6,%7}, {%8,%9}, {%0,%1,%2,%3};\n"
        : "+f"(c[0]),"+f"(c[1]),"+f"(c[2]),"+f"(c[3])
        : "r"(a[0]),"r"(a[1]),"r"(a[2]),"r"(a[3]),"r"(b[0]),"r"(b[1]));
}
__device__ __forceinline__ float ex2f(float x){
    float y; asm("ex2.approx.f32 %0, %1;" : "=f"(y) : "f"(x)); return y;
}

// ============================================================================
// Kernel 1: fused QKV per-head projection, fp16 out. Q pre-scaled by
// log2(e)/sqrt(512) so attention can use raw ex2.
// ============================================================================
__global__ __launch_bounds__(256)
void proj_kernel(const float* __restrict__ Xq, const float* __restrict__ Xk,
                 const float* __restrict__ Xv,
                 const float* __restrict__ Wq, const float* __restrict__ Wk,
                 const float* __restrict__ Wv,
                 __half* __restrict__ Yq, __half* __restrict__ Yk,
                 __half* __restrict__ Yv){
    __shared__ float Wt[64*68];
    __shared__ float Xs[64*68];
    int z = blockIdx.z;
    const float* X = (z==0) ? Xq : (z==1) ? Xk : Xv;
    const float* W = (z==0) ? Wq : (z==1) ? Wk : Wv;
    __half*      Y = (z==0) ? Yq : (z==1) ? Yk : Yv;
    float sc = (z==0) ? 0.06375881311003162f : 1.0f;   // log2(e)/sqrt(512)

    int tid = threadIdx.x;
    int bh = blockIdx.y; int b = bh >> 3; int h = bh & 7;
    int s0 = blockIdx.x * 64;

    #pragma unroll
    for (int r = 0; r < 4; r++){
        int lin = tid + r*256;
        int e  = lin >> 4;
        int d4 = (lin & 15) << 2;
        float4 w = *reinterpret_cast<const float4*>(W + e*64 + d4);
        Wt[(d4+0)*68 + e] = w.x; Wt[(d4+1)*68 + e] = w.y;
        Wt[(d4+2)*68 + e] = w.z; Wt[(d4+3)*68 + e] = w.w;
        float4 xv = *reinterpret_cast<const float4*>(
            X + (((size_t)b*SEQ + s0 + e)*NHEADS + h)*HD + d4);
        *reinterpret_cast<float4*>(Xs + e*68 + d4) = xv;
    }
    __syncthreads();

    int tx = tid & 15, ty = tid >> 4;
    float acc[4][4] = {};
    #pragma unroll 8
    for (int d = 0; d < 64; d++){
        float4 wv = *reinterpret_cast<const float4*>(Wt + d*68 + tx*4);
        #pragma unroll
        for (int i = 0; i < 4; i++){
            float xv = Xs[(ty*4+i)*68 + d];
            acc[i][0] += xv*wv.x; acc[i][1] += xv*wv.y;
            acc[i][2] += xv*wv.z; acc[i][3] += xv*wv.w;
        }
    }
    __half* Yp = Y + ((size_t)bh*SEQ + s0)*HD;
    #pragma unroll
    for (int i = 0; i < 4; i++){
        __half2 h0 = __floats2half2_rn(acc[i][0]*sc, acc[i][1]*sc);
        __half2 h1 = __floats2half2_rn(acc[i][2]*sc, acc[i][3]*sc);
        uint2 u; u.x = *(uint32_t*)&h0; u.y = *(uint32_t*)&h1;
        *reinterpret_cast<uint2*>(Yp + (size_t)(ty*4+i)*HD + tx*4) = u;
    }
}

// ============================================================================
// Kernel 2: single-pass fused attention.
// Phase A: QK (fp16 MMA) -> ex2 -> unnorm P: registers -> PV A-frags directly,
//          and smem-staged coalesced fp16 scratch write; rowsum in registers.
// Phase B: stream scratch * (1/l) -> fp32 attn output.
// 8 warps x 16 q-rows; grid (16, 32); 82432 B smem -> 2 CTAs/SM.
// ============================================================================
#define SM_QH   0
#define SM_K0   18432
#define SM_K1   27648
#define SM_V0   36864
#define SM_V1   46080
#define SM_PS   55296
#define SM_MSK  73728
#define SM_LROW 81920
#define SM_TOTAL 82432

__global__ __launch_bounds__(256, 2)
void attn_kernel(const int* __restrict__ mask, float* __restrict__ attn){
    extern __shared__ char smc[];
    __half*   Ps = (__half*)(smc + SM_PS);
    int*     Msk = (int*)   (smc + SM_MSK);
    float*  Lrow = (float*) (smc + SM_LROW);
    uint32_t qb = saddr(smc + SM_QH);
    uint32_t kbuf[2] = { saddr(smc + SM_K0), saddr(smc + SM_K1) };
    uint32_t vbuf[2] = { saddr(smc + SM_V0), saddr(smc + SM_V1) };

    int tid = threadIdx.x, lane = tid & 31, w = tid >> 5;
    int g = lane >> 2, t = lane & 3;
    int lrow16 = lane & 15;
    int lchunk = (lane >> 4) << 3;
    int bnrow  = (lane & 7) + ((lane >> 3) & 1) * 8;
    int bh = blockIdx.y, b = bh >> 3, h = bh & 7;
    int q0 = blockIdx.x * 128;
    const __half* Qp = g_Qh + (size_t)bh*SEQ*HD;
    const __half* Kp = g_Kh + (size_t)bh*SEQ*HD;
    const __half* Vp = g_Vh + (size_t)bh*SEQ*HD;
    const int* mrow_g = mask + (size_t)b*SEQ;
    __half* Sp = g_Ps + ((size_t)bh*SEQ + q0)*SEQ;

    // per-thread K/V tile load slots: 64 rows x 8 chunks(16B), 2 per thread
    int ldr0 = tid >> 3, ldc = tid & 7;
    int ldr1 = ldr0 + 32;

    // ---- Q tile (sync) + mask row (sync) ----
    #pragma unroll
    for (int j = 0; j < 4; j++){
        int lin = tid + j*256;
        int row = lin >> 3, ch = lin & 7;
        uint4 v = *reinterpret_cast<const uint4*>(Qp + (size_t)(q0+row)*HD + ch*8);
        *reinterpret_cast<uint4*>(smc + SM_QH + row*(STR*2) + ch*16) = v;
    }
    #pragma unroll
    for (int j = 0; j < 2; j++){
        int lin = tid + j*256;
        int4 v = *reinterpret_cast<const int4*>(mrow_g + lin*4);
        *reinterpret_cast<int4*>(Msk + lin*4) = v;
    }

    // preload K(0), V(0)
    cp16(kbuf[0] + ldr0*(STR*2) + ldc*16, Kp + (size_t)ldr0*HD + ldc*8);
    cp16(kbuf[0] + ldr1*(STR*2) + ldc*16, Kp + (size_t)ldr1*HD + ldc*8);
    cp16(vbuf[0] + ldr0*(STR*2) + ldc*16, Vp + (size_t)ldr0*HD + ldc*8);
    cp16(vbuf[0] + ldr1*(STR*2) + ldc*16, Vp + (size_t)ldr1*HD + ldc*8);
    CP_COMMIT();

    float lsum0 = 0.f, lsum1 = 0.f;
    float co[8][4];
    #pragma unroll
    for (int ni=0; ni<8; ni++){ co[ni][0]=0.f; co[ni][1]=0.f; co[ni][2]=0.f; co[ni][3]=0.f; }
    int row0 = w*16 + g;   // local q row of this lane's upper fragment half

    // ======================= PHASE A =======================
    for (int kt = 0; kt < 32; kt++){
        CP_WAIT0();
        __syncthreads();   // K/V(kt) visible; prior readers of buf kt^1 done; Ps copy done
        if (kt < 31){
            const __half* ksrc = Kp + (size_t)(kt+1)*64*HD;
            const __half* vsrc = Vp + (size_t)(kt+1)*64*HD;
            uint32_t kd = kbuf[(kt+1)&1], vd = vbuf[(kt+1)&1];
            cp16(kd + ldr0*(STR*2) + ldc*16, ksrc + (size_t)ldr0*HD + ldc*8);
            cp16(kd + ldr1*(STR*2) + ldc*16, ksrc + (size_t)ldr1*HD + ldc*8);
            cp16(vd + ldr0*(STR*2) + ldc*16, vsrc + (size_t)ldr0*HD + ldc*8);
            cp16(vd + ldr1*(STR*2) + ldc*16, vsrc + (size_t)ldr1*HD + ldc*8);
            CP_COMMIT();
        }
        uint32_t kba = kbuf[kt&1], vba = vbuf[kt&1];
        int kb0 = kt*64;

        // ---- QK: m16 x n64 x k64 per warp ----
        float c[8][4];
        #pragma unroll
        for (int ni=0; ni<8; ni++){ c[ni][0]=0.f; c[ni][1]=0.f; c[ni][2]=0.f; c[ni][3]=0.f; }
        #pragma unroll
        for (int k16 = 0; k16 < 4; k16++){
            uint32_t a[4];
            ldsm4(a, qb + ((w*16+lrow16)*STR + k16*16 + lchunk)*2);
            uint32_t bq[4][4];
            #pragma unroll
            for (int nq=0; nq<4; nq++)
                ldsm4(bq[nq], kba + ((nq*16+bnrow)*STR + k16*16 + lchunk)*2);
            #pragma unroll
            for (int nq=0; nq<4; nq++)
                #pragma unroll
                for (int sub=0; sub<2; sub++){
                    uint32_t bb[2] = { bq[nq][sub], bq[nq][sub+2] };
                    mma16(c[nq*2+sub], a, bb);
                }
        }

        // ---- ex2 + mask + pack; stage to Ps; rowsum ----
        uint32_t ph0[8], ph1[8];
        #pragma unroll
        for (int ni=0; ni<8; ni++){
            int col = kb0 + ni*8 + 2*t;
            bool m0 = (Msk[col] == 0), m1 = (Msk[col+1] == 0);
            float p00 = m0 ? 0.f : ex2f(c[ni][0]);
            float p01 = m1 ? 0.f : ex2f(c[ni][1]);
            float p10 = m0 ? 0.f : ex2f(c[ni][2]);
            float p11 = m1 ? 0.f : ex2f(c[ni][3]);
            lsum0 += p00 + p01;
            lsum1 += p10 + p11;
            __half2 h0v = __floats2half2_rn(p00, p01);
            __half2 h1v = __floats2half2_rn(p10, p11);
            ph0[ni] = *(uint32_t*)&h0v;
            ph1[ni] = *(uint32_t*)&h1v;
            int cl = ni*8 + 2*t;
            *reinterpret_cast<uint32_t*>(Ps + row0*STR + cl)     = ph0[ni];
            *reinterpret_cast<uint32_t*>(Ps + (row0+8)*STR + cl) = ph1[ni];
        }
        __syncthreads();   // Ps tile complete

        // ---- coalesced scratch write (Ps -> gmem fp16) ----
        #pragma unroll
        for (int j = 0; j < 4; j++){
            int lin = tid + j*256;
            int r = lin >> 3, ch = lin & 7;
            uint4 v = *reinterpret_cast<const uint4*>(Ps + r*STR + ch*8);
            *reinterpret_cast<uint4*>(Sp + (size_t)r*SEQ + kb0 + ch*8) = v;
        }

        // ---- PV: A-frags directly from registers ----
        #pragma unroll
        for (int k16 = 0; k16 < 4; k16++){
            uint32_t ap[4] = { ph0[2*k16], ph1[2*k16], ph0[2*k16+1], ph1[2*k16+1] };
            #pragma unroll
            for (int ni2 = 0; ni2 < 4; ni2++){
                uint32_t bv4[4];
                ldsm4t(bv4, vba + ((k16*16+lrow16)*STR + ni2*16 + lchunk)*2);
                mma16(co[ni2*2],   ap, bv4);
                mma16(co[ni2*2+1], ap, bv4+2);
            }
        }
    }

    // ---- rowsum reduce (quad lanes only; each row owned by one warp) ----
    lsum0 += __shfl_xor_sync(0xffffffffu, lsum0, 1);
    lsum0 += __shfl_xor_sync(0xffffffffu, lsum0, 2);
    lsum1 += __shfl_xor_sync(0xffffffffu, lsum1, 1);
    lsum1 += __shfl_xor_sync(0xffffffffu, lsum1, 2);
    if (t == 0){
        Lrow[row0]   = 1.0f / lsum0;
        Lrow[row0+8] = 1.0f / lsum1;
    }
    __syncthreads();   // Lrow ready; also fences all scratch STGs for phase B
    float il0 = Lrow[row0], il1 = Lrow[row0+8];

    // ---- scale O by 1/l, write g_Oh[b, q, h*64+d] ----
    __half* Op = g_Oh + ((size_t)b*SEQ + q0 + w*16)*EMBED + h*HD;
    #pragma unroll
    for (int ni=0; ni<8; ni++){
        int cl = ni*8 + 2*t;
        __half2 o0 = __floats2half2_rn(co[ni][0]*il0, co[ni][1]*il0);
        __half2 o1 = __floats2half2_rn(co[ni][2]*il1, co[ni][3]*il1);
        *reinterpret_cast<__half2*>(Op + (size_t)g*EMBED + cl)     = o0;
        *reinterpret_cast<__half2*>(Op + (size_t)(g+8)*EMBED + cl) = o1;
    }

    // ======================= PHASE B =======================
    // attn[row, :] = scratch[row, :] * (1/l[row]) ; 1 row per iteration.
    float* Ab = attn + ((size_t)bh*SEQ + q0)*SEQ;
    for (int it = 0; it < 128; it++){
        float s = Lrow[it];
        uint4 v = *reinterpret_cast<const uint4*>(Sp + (size_t)it*SEQ + tid*8);
        __half2* hp = (__half2*)&v;
        float4 f0, f1;
        f0.x = __low2float(hp[0])*s;  f0.y = __high2float(hp[0])*s;
        f0.z = __low2float(hp[1])*s;  f0.w = __high2float(hp[1])*s;
        f1.x = __low2float(hp[2])*s;  f1.y = __high2float(hp[2])*s;
        f1.z = __low2float(hp[3])*s;  f1.w = __high2float(hp[3])*s;
        *reinterpret_cast<float4*>(Ab + (size_t)it*SEQ + tid*8)     = f0;
        *reinterpret_cast<float4*>(Ab + (size_t)it*SEQ + tid*8 + 4) = f1;
    }
}

// ============================================================================
// Kernel 3: out = g_Oh @ Wo.T + bo   (M=8192, N=512, K=512)  fp16 MMA
// ============================================================================
#define OP_SMEM_BYTES (128*STR*2 + 64*STR*2)

__global__ __launch_bounds__(256)
void oproj_kernel(const float* __restrict__ Wo, const float* __restrict__ bo,
                  float* __restrict__ out){
    extern __shared__ char osmc[];
    uint32_t ab = saddr(osmc);
    uint32_t bb_ = saddr(osmc + 128*STR*2);
    __half* Bh = (__half*)(osmc + 128*STR*2);

    int tid = threadIdx.x, lane = tid & 31, warp = tid >> 5;
    int wm = warp >> 1, wn = warp & 1, rm = wm*32;
    int g = lane >> 2, t = lane & 3;
    int lrow16 = lane & 15;
    int lchunk = (lane >> 4) << 3;
    int bnrow  = (lane & 7) + ((lane >> 3) & 1) * 8;
    int n0 = blockIdx.x * 64;
    int m0 = blockIdx.y * 128;

    float c[2][4][4];
    #pragma unroll
    for (int mi=0;mi<2;mi++)
        #pragma unroll
        for (int ni=0;ni<4;ni++)
            { c[mi][ni][0]=0.f;c[mi][ni][1]=0.f;c[mi][ni][2]=0.f;c[mi][ni][3]=0.f; }

    const __half* Ap = g_Oh + (size_t)m0*EMBED;

    for (int k0 = 0; k0 < 512; k0 += 64){
        __syncthreads();
        #pragma unroll
        for (int j = 0; j < 4; j++){
            int lin = tid + j*256;
            int row = lin >> 3, ch = lin & 7;
            uint4 v = *reinterpret_cast<const uint4*>(Ap + (size_t)row*EMBED + k0 + ch*8);
            *reinterpret_cast<uint4*>(osmc + row*(STR*2) + ch*16) = v;
        }
        #pragma unroll
        for (int j = 0; j < 2; j++){
            int lin = tid + j*256;
            int row = lin >> 3, c8 = (lin & 7) * 8;
            const float* src = Wo + (size_t)(n0+row)*512 + k0 + c8;
            float4 v0 = *reinterpret_cast<const float4*>(src);
            float4 v1 = *reinterpret_cast<const float4*>(src + 4);
            __half2 h0 = __floats2half2_rn(v0.x, v0.y);
            __half2 h1 = __floats2half2_rn(v0.z, v0.w);
            __half2 h2 = __floats2half2_rn(v1.x, v1.y);
            __half2 h3 = __floats2half2_rn(v1.z, v1.w);
            uint4 u; u.x = *(uint32_t*)&h0; u.y = *(uint32_t*)&h1;
            u.z = *(uint32_t*)&h2; u.w = *(uint32_t*)&h3;
            *reinterpret_cast<uint4*>((char*)Bh + row*(STR*2) + c8*2) = u;
        }
        __syncthreads();

        #pragma unroll
        for (int k16 = 0; k16 < 4; k16++){
            uint32_t a[2][4];
            #pragma unroll
            for (int mi=0; mi<2; mi++)
                ldsm4(a[mi], ab + ((rm+mi*16+lrow16)*STR + k16*16 + lchunk)*2);
            uint32_t bq[2][4];
            #pragma unroll
            for (int pr=0; pr<2; pr++)
                ldsm4(bq[pr], bb_ + ((wn*32+pr*16+bnrow)*STR + k16*16 + lchunk)*2);
            #pragma unroll
            for (int mi=0; mi<2; mi++)
                #pragma unroll
                for (int pr=0; pr<2; pr++)
                    #pragma unroll
                    for (int sub=0; sub<2; sub++){
                        uint32_t bb2[2] = { bq[pr][sub], bq[pr][sub+2] };
                        mma16(c[mi][pr*2+sub], a[mi], bb2);
                    }
        }
    }
    #pragma unroll
    for (int mi=0;mi<2;mi++)
        #pragma unroll
        for (int half=0; half<2; half++){
            int row = rm + mi*16 + half*8 + g;
            #pragma unroll
            for (int ni=0; ni<4; ni++){
                int col = wn*32 + ni*8 + 2*t;
                float2 bv = *reinterpret_cast<const float2*>(bo + n0 + col);
                *reinterpret_cast<float2*>(out + (size_t)(m0+row)*512 + n0 + col) =
                    make_float2(c[mi][ni][half*2] + bv.x, c[mi][ni][half*2+1] + bv.y);
            }
        }
}

// ============================================================================
// launch
// ============================================================================
extern "C" void kernel_launch(void* const* d_in, const int* in_sizes, int n_in,
                              void* d_out, int out_size){
    (void)in_sizes; (void)n_in; (void)out_size;
    const float* values = (const float*)d_in[0];
    const float* keys   = (const float*)d_in[1];
    const float* query  = (const float*)d_in[2];
    const int*   mask   = (const int*)d_in[3];
    const float* Wv     = (const float*)d_in[4];
    const float* Wk     = (const float*)d_in[5];
    const float* Wq     = (const float*)d_in[6];
    const float* Wo     = (const float*)d_in[7];
    const float* bo     = (const float*)d_in[8];

    float* out  = (float*)d_out;                              // [B,S,E]
    float* attn = out + (size_t)BATCH*SEQ*EMBED;              // [B,H,S,S]

    __half *qptr, *kptr, *vptr;
    cudaGetSymbolAddress((void**)&qptr, g_Qh);
    cudaGetSymbolAddress((void**)&kptr, g_Kh);
    cudaGetSymbolAddress((void**)&vptr, g_Vh);

    cudaFuncSetAttribute(attn_kernel, cudaFuncAttributeMaxDynamicSharedMemorySize,
                         SM_TOTAL);
    cudaFuncSetAttribute(oproj_kernel, cudaFuncAttributeMaxDynamicSharedMemorySize,
                         OP_SMEM_BYTES);

    proj_kernel<<<dim3(SEQ/64, BATCH*NHEADS, 3), 256>>>(
        query, keys, values, Wq, Wk, Wv, qptr, kptr, vptr);

    attn_kernel<<<dim3(SEQ/128, BATCH*NHEADS), 256, SM_TOTAL>>>(mask, attn);

    oproj_kernel<<<dim3(EMBED/64, (BATCH*SEQ)/128), 256, OP_SMEM_BYTES>>>(Wo, bo, out);
}

// round 11
// speedup vs baseline: 1.1883x; 1.1883x over previous
#include <cuda_runtime.h>
#include <cuda_fp16.h>
#include <cstdint>

#define NHEADS 8
#define EMBED  512
#define HD     64
#define BATCH  4
#define SEQ    2048
#define STR    72   // smem tile stride in halves (144B rows)

// ---- scratch (allocation-free: __device__ globals) ----
__device__ __half g_Qh[BATCH*NHEADS*SEQ*HD];   // pre-scaled by log2(e)/sqrt(512)
__device__ __half g_Kh[BATCH*NHEADS*SEQ*HD];
__device__ __half g_Vh[BATCH*NHEADS*SEQ*HD];
__device__ __half g_Oh[BATCH*SEQ*EMBED];       // attention output pre-Wo (fp16)

__device__ __forceinline__ uint32_t saddr(const void* p){
    return (uint32_t)__cvta_generic_to_shared(p);
}
__device__ __forceinline__ void cp16(uint32_t d, const void* s){
    asm volatile("cp.async.cg.shared.global [%0], [%1], 16;\n" :: "r"(d), "l"(s));
}
#define CP_COMMIT() asm volatile("cp.async.commit_group;\n")
#define CP_WAIT0()  asm volatile("cp.async.wait_group 0;\n")

__device__ __forceinline__ void ldsm4(uint32_t* r, uint32_t a){
    asm volatile("ldmatrix.sync.aligned.m8n8.x4.shared.b16 {%0,%1,%2,%3}, [%4];\n"
        : "=r"(r[0]),"=r"(r[1]),"=r"(r[2]),"=r"(r[3]) : "r"(a));
}
__device__ __forceinline__ void ldsm4t(uint32_t* r, uint32_t a){
    asm volatile("ldmatrix.sync.aligned.m8n8.x4.trans.shared.b16 {%0,%1,%2,%3}, [%4];\n"
        : "=r"(r[0]),"=r"(r[1]),"=r"(r[2]),"=r"(r[3]) : "r"(a));
}
__device__ __forceinline__ void mma16(float* c, const uint32_t* a, const uint32_t* b){
    asm volatile(
        "mma.sync.aligned.m16n8k16.row.col.f32.f16.f16.f32 "
        "{%0,%1,%2,%3}, {%4,%5,%6,%7}, {%8,%9}, {%0,%1,%2,%3};\n"
        : "+f"(c[0]),"+f"(c[1]),"+f"(c[2]),"+f"(c[3])
        : "r"(a[0]),"r"(a[1]),"r"(a[2]),"r"(a[3]),"r"(b[0]),"r"(b[1]));
}
__device__ __forceinline__ float ex2f(float x){
    float y; asm("ex2.approx.f32 %0, %1;" : "=f"(y) : "f"(x)); return y;
}

// ============================================================================
// Kernel 1: fused QKV per-head projection, fp16 out. Q pre-scaled by
// log2(e)/sqrt(512) so attention uses a single ex2.
// ============================================================================
__global__ __launch_bounds__(256)
void proj_kernel(const float* __restrict__ Xq, const float* __restrict__ Xk,
                 const float* __restrict__ Xv,
                 const float* __restrict__ Wq, const float* __restrict__ Wk,
                 const float* __restrict__ Wv,
                 __half* __restrict__ Yq, __half* __restrict__ Yk,
                 __half* __restrict__ Yv){
    __shared__ float Wt[64*68];
    __shared__ float Xs[64*68];
    int z = blockIdx.z;
    const float* X = (z==0) ? Xq : (z==1) ? Xk : Xv;
    const float* W = (z==0) ? Wq : (z==1) ? Wk : Wv;
    __half*      Y = (z==0) ? Yq : (z==1) ? Yk : Yv;
    float sc = (z==0) ? 0.06375881311003162f : 1.0f;   // log2(e)/sqrt(512)

    int tid = threadIdx.x;
    int bh = blockIdx.y; int b = bh >> 3; int h = bh & 7;
    int s0 = blockIdx.x * 64;

    #pragma unroll
    for (int r = 0; r < 4; r++){
        int lin = tid + r*256;
        int e  = lin >> 4;
        int d4 = (lin & 15) << 2;
        float4 w = *reinterpret_cast<const float4*>(W + e*64 + d4);
        Wt[(d4+0)*68 + e] = w.x; Wt[(d4+1)*68 + e] = w.y;
        Wt[(d4+2)*68 + e] = w.z; Wt[(d4+3)*68 + e] = w.w;
        float4 xv = *reinterpret_cast<const float4*>(
            X + (((size_t)b*SEQ + s0 + e)*NHEADS + h)*HD + d4);
        *reinterpret_cast<float4*>(Xs + e*68 + d4) = xv;
    }
    __syncthreads();

    int tx = tid & 15, ty = tid >> 4;
    float acc[4][4] = {};
    #pragma unroll 8
    for (int d = 0; d < 64; d++){
        float4 wv = *reinterpret_cast<const float4*>(Wt + d*68 + tx*4);
        #pragma unroll
        for (int i = 0; i < 4; i++){
            float xv = Xs[(ty*4+i)*68 + d];
            acc[i][0] += xv*wv.x; acc[i][1] += xv*wv.y;
            acc[i][2] += xv*wv.z; acc[i][3] += xv*wv.w;
        }
    }
    __half* Yp = Y + ((size_t)bh*SEQ + s0)*HD;
    #pragma unroll
    for (int i = 0; i < 4; i++){
        __half2 h0 = __floats2half2_rn(acc[i][0]*sc, acc[i][1]*sc);
        __half2 h1 = __floats2half2_rn(acc[i][2]*sc, acc[i][3]*sc);
        uint2 u; u.x = *(uint32_t*)&h0; u.y = *(uint32_t*)&h1;
        *reinterpret_cast<uint2*>(Yp + (size_t)(ty*4+i)*HD + tx*4) = u;
    }
}

// ============================================================================
// Kernel 2: two-pass fused attention, 8 warps x 16 q-rows (warp owns full
// n=64). Pass 1: rowsum of ex2 (register reduce, no smem). Pass 2: QK again,
// P normalized in registers -> fp32 attn store + direct PV A-frags.
// grid (16, 32), 256 threads, 63488 B smem -> 2 CTAs/SM.
// ============================================================================
#define SM_QH   0
#define SM_K0   18432
#define SM_K1   27648
#define SM_V0   36864
#define SM_V1   46080
#define SM_MSK  55296
#define SM_TOTAL 63488

__global__ __launch_bounds__(256, 2)
void attn_kernel(const int* __restrict__ mask, float* __restrict__ attn){
    extern __shared__ char smc[];
    int* Msk = (int*)(smc + SM_MSK);
    uint32_t qb = saddr(smc + SM_QH);
    uint32_t kbuf[2] = { saddr(smc + SM_K0), saddr(smc + SM_K1) };
    uint32_t vbuf[2] = { saddr(smc + SM_V0), saddr(smc + SM_V1) };

    int tid = threadIdx.x, lane = tid & 31, w = tid >> 5;
    int g = lane >> 2, t = lane & 3;
    int lrow16 = lane & 15;
    int lchunk = (lane >> 4) << 3;
    int bnrow  = (lane & 7) + ((lane >> 3) & 1) * 8;
    int bh = blockIdx.y, b = bh >> 3, h = bh & 7;
    int q0 = blockIdx.x * 128;
    const __half* Qp = g_Qh + (size_t)bh*SEQ*HD;
    const __half* Kp = g_Kh + (size_t)bh*SEQ*HD;
    const __half* Vp = g_Vh + (size_t)bh*SEQ*HD;
    const int* mrow_g = mask + (size_t)b*SEQ;
    int row0 = w*16 + g;   // this lane's upper fragment row (local)

    // per-thread K/V tile load slots: 64 rows x 8 chunks(16B), 2 per thread
    int ldr0 = tid >> 3, ldc = tid & 7;
    int ldr1 = ldr0 + 32;

    // ---- Q tile (sync) + mask row (sync) ----
    #pragma unroll
    for (int j = 0; j < 4; j++){
        int lin = tid + j*256;
        int row = lin >> 3, ch = lin & 7;
        uint4 v = *reinterpret_cast<const uint4*>(Qp + (size_t)(q0+row)*HD + ch*8);
        *reinterpret_cast<uint4*>(smc + SM_QH + row*(STR*2) + ch*16) = v;
    }
    #pragma unroll
    for (int j = 0; j < 2; j++){
        int lin = tid + j*256;
        int4 v = *reinterpret_cast<const int4*>(mrow_g + lin*4);
        *reinterpret_cast<int4*>(Msk + lin*4) = v;
    }

    // preload K(0)
    cp16(kbuf[0] + ldr0*(STR*2) + ldc*16, Kp + (size_t)ldr0*HD + ldc*8);
    cp16(kbuf[0] + ldr1*(STR*2) + ldc*16, Kp + (size_t)ldr1*HD + ldc*8);
    CP_COMMIT();

    // ---------------- PASS 1: rowsum of ex2(QK) ----------------
    float lsum0 = 0.f, lsum1 = 0.f;
    for (int kt = 0; kt < 32; kt++){
        CP_WAIT0();
        __syncthreads();
        if (kt < 31){
            const __half* src = Kp + (size_t)(kt+1)*64*HD;
            uint32_t dst = kbuf[(kt+1)&1];
            cp16(dst + ldr0*(STR*2) + ldc*16, src + (size_t)ldr0*HD + ldc*8);
            cp16(dst + ldr1*(STR*2) + ldc*16, src + (size_t)ldr1*HD + ldc*8);
            CP_COMMIT();
        }
        uint32_t kba = kbuf[kt&1];
        int kb0 = kt*64;

        float c[8][4];
        #pragma unroll
        for (int ni=0; ni<8; ni++){ c[ni][0]=0.f; c[ni][1]=0.f; c[ni][2]=0.f; c[ni][3]=0.f; }
        #pragma unroll
        for (int k16 = 0; k16 < 4; k16++){
            uint32_t a[4];
            ldsm4(a, qb + ((w*16+lrow16)*STR + k16*16 + lchunk)*2);
            uint32_t bq[4][4];
            #pragma unroll
            for (int nq=0; nq<4; nq++)
                ldsm4(bq[nq], kba + ((nq*16+bnrow)*STR + k16*16 + lchunk)*2);
            #pragma unroll
            for (int nq=0; nq<4; nq++)
                #pragma unroll
                for (int sub=0; sub<2; sub++){
                    uint32_t bb[2] = { bq[nq][sub], bq[nq][sub+2] };
                    mma16(c[nq*2+sub], a, bb);
                }
        }
        #pragma unroll
        for (int ni=0; ni<8; ni++){
            int col = kb0 + ni*8 + 2*t;
            bool m0 = (Msk[col] == 0), m1 = (Msk[col+1] == 0);
            lsum0 += (m0?0.f:ex2f(c[ni][0])) + (m1?0.f:ex2f(c[ni][1]));
            lsum1 += (m0?0.f:ex2f(c[ni][2])) + (m1?0.f:ex2f(c[ni][3]));
        }
    }
    // each row owned by one warp: reduce across the 4 t-lanes only
    lsum0 += __shfl_xor_sync(0xffffffffu, lsum0, 1);
    lsum0 += __shfl_xor_sync(0xffffffffu, lsum0, 2);
    lsum1 += __shfl_xor_sync(0xffffffffu, lsum1, 1);
    lsum1 += __shfl_xor_sync(0xffffffffu, lsum1, 2);
    float il0 = 1.0f / lsum0;
    float il1 = 1.0f / lsum1;

    // ---------------- PASS 2: normalized P -> attn + PV ----------------
    float co[8][4];
    #pragma unroll
    for (int ni=0; ni<8; ni++){ co[ni][0]=0.f; co[ni][1]=0.f; co[ni][2]=0.f; co[ni][3]=0.f; }

    // preload K(0)+V(0)
    cp16(kbuf[0] + ldr0*(STR*2) + ldc*16, Kp + (size_t)ldr0*HD + ldc*8);
    cp16(kbuf[0] + ldr1*(STR*2) + ldc*16, Kp + (size_t)ldr1*HD + ldc*8);
    cp16(vbuf[0] + ldr0*(STR*2) + ldc*16, Vp + (size_t)ldr0*HD + ldc*8);
    cp16(vbuf[0] + ldr1*(STR*2) + ldc*16, Vp + (size_t)ldr1*HD + ldc*8);
    CP_COMMIT();

    float* ar0 = attn + ((size_t)bh*SEQ + q0 + row0)*SEQ;
    float* ar1 = ar0 + (size_t)8*SEQ;

    for (int kt = 0; kt < 32; kt++){
        CP_WAIT0();
        __syncthreads();
        if (kt < 31){
            const __half* ksrc = Kp + (size_t)(kt+1)*64*HD;
            const __half* vsrc = Vp + (size_t)(kt+1)*64*HD;
            uint32_t kd = kbuf[(kt+1)&1], vd = vbuf[(kt+1)&1];
            cp16(kd + ldr0*(STR*2) + ldc*16, ksrc + (size_t)ldr0*HD + ldc*8);
            cp16(kd + ldr1*(STR*2) + ldc*16, ksrc + (size_t)ldr1*HD + ldc*8);
            cp16(vd + ldr0*(STR*2) + ldc*16, vsrc + (size_t)ldr0*HD + ldc*8);
            cp16(vd + ldr1*(STR*2) + ldc*16, vsrc + (size_t)ldr1*HD + ldc*8);
            CP_COMMIT();
        }
        uint32_t kba = kbuf[kt&1], vba = vbuf[kt&1];
        int kb0 = kt*64;

        // ---- QK ----
        float c[8][4];
        #pragma unroll
        for (int ni=0; ni<8; ni++){ c[ni][0]=0.f; c[ni][1]=0.f; c[ni][2]=0.f; c[ni][3]=0.f; }
        #pragma unroll
        for (int k16 = 0; k16 < 4; k16++){
            uint32_t a[4];
            ldsm4(a, qb + ((w*16+lrow16)*STR + k16*16 + lchunk)*2);
            uint32_t bq[4][4];
            #pragma unroll
            for (int nq=0; nq<4; nq++)
                ldsm4(bq[nq], kba + ((nq*16+bnrow)*STR + k16*16 + lchunk)*2);
            #pragma unroll
            for (int nq=0; nq<4; nq++)
                #pragma unroll
                for (int sub=0; sub<2; sub++){
                    uint32_t bb[2] = { bq[nq][sub], bq[nq][sub+2] };
                    mma16(c[nq*2+sub], a, bb);
                }
        }

        // ---- normalized P: fp32 attn store + fp16 pack for PV ----
        uint32_t ph0[8], ph1[8];
        #pragma unroll
        for (int ni=0; ni<8; ni++){
            int cl = ni*8 + 2*t;
            int col = kb0 + cl;
            bool m0 = (Msk[col] == 0), m1 = (Msk[col+1] == 0);
            float p00 = m0 ? 0.f : ex2f(c[ni][0]) * il0;
            float p01 = m1 ? 0.f : ex2f(c[ni][1]) * il0;
            float p10 = m0 ? 0.f : ex2f(c[ni][2]) * il1;
            float p11 = m1 ? 0.f : ex2f(c[ni][3]) * il1;
            *reinterpret_cast<float2*>(ar0 + col) = make_float2(p00, p01);
            *reinterpret_cast<float2*>(ar1 + col) = make_float2(p10, p11);
            __half2 h0v = __floats2half2_rn(p00, p01);
            __half2 h1v = __floats2half2_rn(p10, p11);
            ph0[ni] = *(uint32_t*)&h0v;
            ph1[ni] = *(uint32_t*)&h1v;
        }

        // ---- PV: A-frags directly from registers ----
        #pragma unroll
        for (int k16 = 0; k16 < 4; k16++){
            uint32_t ap[4] = { ph0[2*k16], ph1[2*k16], ph0[2*k16+1], ph1[2*k16+1] };
            #pragma unroll
            for (int ni2 = 0; ni2 < 4; ni2++){
                uint32_t bv4[4];
                ldsm4t(bv4, vba + ((k16*16+lrow16)*STR + ni2*16 + lchunk)*2);
                mma16(co[ni2*2],   ap, bv4);
                mma16(co[ni2*2+1], ap, bv4+2);
            }
        }
    }

    // ---- write O (already normalized) to g_Oh[b, q, h*64+d] ----
    __half* Op = g_Oh + ((size_t)b*SEQ + q0 + w*16)*EMBED + h*HD;
    #pragma unroll
    for (int ni=0; ni<8; ni++){
        int cl = ni*8 + 2*t;
        __half2 o0 = __floats2half2_rn(co[ni][0], co[ni][1]);
        __half2 o1 = __floats2half2_rn(co[ni][2], co[ni][3]);
        *reinterpret_cast<__half2*>(Op + (size_t)g*EMBED + cl)     = o0;
        *reinterpret_cast<__half2*>(Op + (size_t)(g+8)*EMBED + cl) = o1;
    }
}

// ============================================================================
// Kernel 3: out = g_Oh @ Wo.T + bo   (M=8192, N=512, K=512)  fp16 MMA
// ============================================================================
#define OP_SMEM_BYTES (128*STR*2 + 64*STR*2)

__global__ __launch_bounds__(256)
void oproj_kernel(const float* __restrict__ Wo, const float* __restrict__ bo,
                  float* __restrict__ out){
    extern __shared__ char osmc[];
    uint32_t ab = saddr(osmc);
    uint32_t bb_ = saddr(osmc + 128*STR*2);
    __half* Bh = (__half*)(osmc + 128*STR*2);

    int tid = threadIdx.x, lane = tid & 31, warp = tid >> 5;
    int wm = warp >> 1, wn = warp & 1, rm = wm*32;
    int g = lane >> 2, t = lane & 3;
    int lrow16 = lane & 15;
    int lchunk = (lane >> 4) << 3;
    int bnrow  = (lane & 7) + ((lane >> 3) & 1) * 8;
    int n0 = blockIdx.x * 64;
    int m0 = blockIdx.y * 128;

    float c[2][4][4];
    #pragma unroll
    for (int mi=0;mi<2;mi++)
        #pragma unroll
        for (int ni=0;ni<4;ni++)
            { c[mi][ni][0]=0.f;c[mi][ni][1]=0.f;c[mi][ni][2]=0.f;c[mi][ni][3]=0.f; }

    const __half* Ap = g_Oh + (size_t)m0*EMBED;

    for (int k0 = 0; k0 < 512; k0 += 64){
        __syncthreads();
        #pragma unroll
        for (int j = 0; j < 4; j++){
            int lin = tid + j*256;
            int row = lin >> 3, ch = lin & 7;
            uint4 v = *reinterpret_cast<const uint4*>(Ap + (size_t)row*EMBED + k0 + ch*8);
            *reinterpret_cast<uint4*>(osmc + row*(STR*2) + ch*16) = v;
        }
        #pragma unroll
        for (int j = 0; j < 2; j++){
            int lin = tid + j*256;
            int row = lin >> 3, c8 = (lin & 7) * 8;
            const float* src = Wo + (size_t)(n0+row)*512 + k0 + c8;
            float4 v0 = *reinterpret_cast<const float4*>(src);
            float4 v1 = *reinterpret_cast<const float4*>(src + 4);
            __half2 h0 = __floats2half2_rn(v0.x, v0.y);
            __half2 h1 = __floats2half2_rn(v0.z, v0.w);
            __half2 h2 = __floats2half2_rn(v1.x, v1.y);
            __half2 h3 = __floats2half2_rn(v1.z, v1.w);
            uint4 u; u.x = *(uint32_t*)&h0; u.y = *(uint32_t*)&h1;
            u.z = *(uint32_t*)&h2; u.w = *(uint32_t*)&h3;
            *reinterpret_cast<uint4*>((char*)Bh + row*(STR*2) + c8*2) = u;
        }
        __syncthreads();

        #pragma unroll
        for (int k16 = 0; k16 < 4; k16++){
            uint32_t a[2][4];
            #pragma unroll
            for (int mi=0; mi<2; mi++)
                ldsm4(a[mi], ab + ((rm+mi*16+lrow16)*STR + k16*16 + lchunk)*2);
            uint32_t bq[2][4];
            #pragma unroll
            for (int pr=0; pr<2; pr++)
                ldsm4(bq[pr], bb_ + ((wn*32+pr*16+bnrow)*STR + k16*16 + lchunk)*2);
            #pragma unroll
            for (int mi=0; mi<2; mi++)
                #pragma unroll
                for (int pr=0; pr<2; pr++)
                    #pragma unroll
                    for (int sub=0; sub<2; sub++){
                        uint32_t bb2[2] = { bq[pr][sub], bq[pr][sub+2] };
                        mma16(c[mi][pr*2+sub], a[mi], bb2);
                    }
        }
    }
    #pragma unroll
    for (int mi=0;mi<2;mi++)
        #pragma unroll
        for (int half=0; half<2; half++){
            int row = rm + mi*16 + half*8 + g;
            #pragma unroll
            for (int ni=0; ni<4; ni++){
                int col = wn*32 + ni*8 + 2*t;
                float2 bv = *reinterpret_cast<const float2*>(bo + n0 + col);
                *reinterpret_cast<float2*>(out + (size_t)(m0+row)*512 + n0 + col) =
                    make_float2(c[mi][ni][half*2] + bv.x, c[mi][ni][half*2+1] + bv.y);
            }
        }
}

// ============================================================================
// launch
// ============================================================================
extern "C" void kernel_launch(void* const* d_in, const int* in_sizes, int n_in,
                              void* d_out, int out_size){
    (void)in_sizes; (void)n_in; (void)out_size;
    const float* values = (const float*)d_in[0];
    const float* keys   = (const float*)d_in[1];
    const float* query  = (const float*)d_in[2];
    const int*   mask   = (const int*)d_in[3];
    const float* Wv     = (const float*)d_in[4];
    const float* Wk     = (const float*)d_in[5];
    const float* Wq     = (const float*)d_in[6];
    const float* Wo     = (const float*)d_in[7];
    const float* bo     = (const float*)d_in[8];

    float* out  = (float*)d_out;                              // [B,S,E]
    float* attn = out + (size_t)BATCH*SEQ*EMBED;              // [B,H,S,S]

    __half *qptr, *kptr, *vptr;
    cudaGetSymbolAddress((void**)&qptr, g_Qh);
    cudaGetSymbolAddress((void**)&kptr, g_Kh);
    cudaGetSymbolAddress((void**)&vptr, g_Vh);

    cudaFuncSetAttribute(attn_kernel, cudaFuncAttributeMaxDynamicSharedMemorySize,
                         SM_TOTAL);
    cudaFuncSetAttribute(oproj_kernel, cudaFuncAttributeMaxDynamicSharedMemorySize,
                         OP_SMEM_BYTES);

    proj_kernel<<<dim3(SEQ/64, BATCH*NHEADS, 3), 256>>>(
        query, keys, values, Wq, Wk, Wv, qptr, kptr, vptr);

    attn_kernel<<<dim3(SEQ/128, BATCH*NHEADS), 256, SM_TOTAL>>>(mask, attn);

    oproj_kernel<<<dim3(EMBED/64, (BATCH*SEQ)/128), 256, OP_SMEM_BYTES>>>(Wo, bo, out);
}

// round 12
// speedup vs baseline: 1.2857x; 1.0819x over previous
#include <cuda_runtime.h>
#include <cuda_fp16.h>
#include <cstdint>

#define NHEADS 8
#define EMBED  512
#define HD     64
#define BATCH  4
#define SEQ    2048
#define STR    72   // smem tile stride in halves (144B rows)

// ---- scratch (allocation-free: __device__ globals) ----
__device__ __half g_Qh[BATCH*NHEADS*SEQ*HD];   // pre-scaled by log2(e)/sqrt(512)
__device__ __half g_Kh[BATCH*NHEADS*SEQ*HD];
__device__ __half g_Vh[BATCH*NHEADS*SEQ*HD];
__device__ __half g_Oh[BATCH*SEQ*EMBED];       // attention output pre-Wo (fp16)

__device__ __forceinline__ uint32_t saddr(const void* p){
    return (uint32_t)__cvta_generic_to_shared(p);
}
__device__ __forceinline__ void cp16(uint32_t d, const void* s){
    asm volatile("cp.async.cg.shared.global [%0], [%1], 16;\n" :: "r"(d), "l"(s));
}
#define CP_COMMIT() asm volatile("cp.async.commit_group;\n")
#define CP_WAIT0()  asm volatile("cp.async.wait_group 0;\n")
#define CP_WAIT1()  asm volatile("cp.async.wait_group 1;\n")

__device__ __forceinline__ void ldsm4(uint32_t* r, uint32_t a){
    asm volatile("ldmatrix.sync.aligned.m8n8.x4.shared.b16 {%0,%1,%2,%3}, [%4];\n"
        : "=r"(r[0]),"=r"(r[1]),"=r"(r[2]),"=r"(r[3]) : "r"(a));
}
__device__ __forceinline__ void ldsm4t(uint32_t* r, uint32_t a){
    asm volatile("ldmatrix.sync.aligned.m8n8.x4.trans.shared.b16 {%0,%1,%2,%3}, [%4];\n"
        : "=r"(r[0]),"=r"(r[1]),"=r"(r[2]),"=r"(r[3]) : "r"(a));
}
__device__ __forceinline__ void mma16(float* c, const uint32_t* a, const uint32_t* b){
    asm volatile(
        "mma.sync.aligned.m16n8k16.row.col.f32.f16.f16.f32 "
        "{%0,%1,%2,%3}, {%4,%5,%6,%7}, {%8,%9}, {%0,%1,%2,%3};\n"
        : "+f"(c[0]),"+f"(c[1]),"+f"(c[2]),"+f"(c[3])
        : "r"(a[0]),"r"(a[1]),"r"(a[2]),"r"(a[3]),"r"(b[0]),"r"(b[1]));
}
__device__ __forceinline__ float ex2f(float x){
    float y; asm("ex2.approx.f32 %0, %1;" : "=f"(y) : "f"(x)); return y;
}

// ============================================================================
// Kernel 1: fused QKV per-head projection via fp16 MMA.
// CTA = 128 seq rows x one (b,h) x one of Q/K/V (z). 8 warps x 16 rows.
// Q output pre-scaled by log2(e)/sqrt(512).
// ============================================================================
#define PJ_X  0                      // 128 x STR halves
#define PJ_W  18432                  // 64 x STR halves
#define PJ_TOTAL (18432 + 9216)

__global__ __launch_bounds__(256)
void proj_kernel(const float* __restrict__ Xq, const float* __restrict__ Xk,
                 const float* __restrict__ Xv,
                 const float* __restrict__ Wq, const float* __restrict__ Wk,
                 const float* __restrict__ Wv,
                 __half* __restrict__ Yq, __half* __restrict__ Yk,
                 __half* __restrict__ Yv){
    extern __shared__ char psm[];
    uint32_t xb = saddr(psm + PJ_X);
    uint32_t wb = saddr(psm + PJ_W);

    int z = blockIdx.z;
    const float* X = (z==0) ? Xq : (z==1) ? Xk : Xv;
    const float* W = (z==0) ? Wq : (z==1) ? Wk : Wv;
    __half*      Y = (z==0) ? Yq : (z==1) ? Yk : Yv;
    float sc = (z==0) ? 0.06375881311003162f : 1.0f;   // log2(e)/sqrt(512)

    int tid = threadIdx.x, lane = tid & 31, w = tid >> 5;
    int g = lane >> 2, t = lane & 3;
    int lrow16 = lane & 15;
    int lchunk = (lane >> 4) << 3;
    int bnrow  = (lane & 7) + ((lane >> 3) & 1) * 8;
    int bh = blockIdx.y; int b = bh >> 3; int h = bh & 7;
    int s0 = blockIdx.x * 128;

    // X tile: 128 rows x 64 floats -> fp16 smem. 2048 float4 slots, 8/thread.
    #pragma unroll
    for (int j = 0; j < 8; j++){
        int lin = tid + j*256;
        int row = lin >> 4, c4 = (lin & 15) << 2;
        float4 v = *reinterpret_cast<const float4*>(
            X + (((size_t)b*SEQ + s0 + row)*NHEADS + h)*HD + c4);
        __half2 h0 = __floats2half2_rn(v.x, v.y);
        __half2 h1 = __floats2half2_rn(v.z, v.w);
        uint2 u; u.x = *(uint32_t*)&h0; u.y = *(uint32_t*)&h1;
        *reinterpret_cast<uint2*>(psm + PJ_X + (row*STR + c4)*2) = u;
    }
    // W tile: 64 rows x 64 floats -> fp16 smem. 1024 float4, 4/thread.
    #pragma unroll
    for (int j = 0; j < 4; j++){
        int lin = tid + j*256;
        int row = lin >> 4, c4 = (lin & 15) << 2;
        float4 v = *reinterpret_cast<const float4*>(W + (size_t)row*64 + c4);
        __half2 h0 = __floats2half2_rn(v.x, v.y);
        __half2 h1 = __floats2half2_rn(v.z, v.w);
        uint2 u; u.x = *(uint32_t*)&h0; u.y = *(uint32_t*)&h1;
        *reinterpret_cast<uint2*>(psm + PJ_W + (row*STR + c4)*2) = u;
    }
    __syncthreads();

    // MMA: warp w -> rows w*16..w*16+15, n = 64 (W outputs), k = 64
    float c[8][4];
    #pragma unroll
    for (int ni=0; ni<8; ni++){ c[ni][0]=0.f; c[ni][1]=0.f; c[ni][2]=0.f; c[ni][3]=0.f; }
    #pragma unroll
    for (int k16 = 0; k16 < 4; k16++){
        uint32_t a[4];
        ldsm4(a, xb + ((w*16+lrow16)*STR + k16*16 + lchunk)*2);
        uint32_t bq[4][4];
        #pragma unroll
        for (int nq=0; nq<4; nq++)
            ldsm4(bq[nq], wb + ((nq*16+bnrow)*STR + k16*16 + lchunk)*2);
        #pragma unroll
        for (int nq=0; nq<4; nq++)
            #pragma unroll
            for (int sub=0; sub<2; sub++){
                uint32_t bb[2] = { bq[nq][sub], bq[nq][sub+2] };
                mma16(c[nq*2+sub], a, bb);
            }
    }

    __half* Yp = Y + ((size_t)bh*SEQ + s0 + w*16)*HD;
    #pragma unroll
    for (int ni=0; ni<8; ni++){
        int cl = ni*8 + 2*t;
        __half2 o0 = __floats2half2_rn(c[ni][0]*sc, c[ni][1]*sc);
        __half2 o1 = __floats2half2_rn(c[ni][2]*sc, c[ni][3]*sc);
        *reinterpret_cast<__half2*>(Yp + (size_t)g*HD + cl)     = o0;
        *reinterpret_cast<__half2*>(Yp + (size_t)(g+8)*HD + cl) = o1;
    }
}

// ============================================================================
// Kernel 2: two-pass fused attention, 8 warps x 16 q-rows, 3-stage cp.async
// ring (wait_group 1). Pass 1: rowsum of ex2. Pass 2: normalized P -> attn
// (streaming stores) + register-direct PV.
// grid (16, 32), 256 threads, 81920 B smem -> 2 CTAs/SM.
// ============================================================================
#define SM_QH   0
#define SM_K0   18432
#define SM_V0   46080
#define SM_MSK  73728
#define SM_TOTAL 81920
#define KBUF    9216

__global__ __launch_bounds__(256, 2)
void attn_kernel(const int* __restrict__ mask, float* __restrict__ attn){
    extern __shared__ char smc[];
    int* Msk = (int*)(smc + SM_MSK);
    uint32_t qb = saddr(smc + SM_QH);
    uint32_t kbuf[3] = { saddr(smc + SM_K0), saddr(smc + SM_K0 + KBUF),
                         saddr(smc + SM_K0 + 2*KBUF) };
    uint32_t vbuf[3] = { saddr(smc + SM_V0), saddr(smc + SM_V0 + KBUF),
                         saddr(smc + SM_V0 + 2*KBUF) };

    int tid = threadIdx.x, lane = tid & 31, w = tid >> 5;
    int g = lane >> 2, t = lane & 3;
    int lrow16 = lane & 15;
    int lchunk = (lane >> 4) << 3;
    int bnrow  = (lane & 7) + ((lane >> 3) & 1) * 8;
    int bh = blockIdx.y, b = bh >> 3, h = bh & 7;
    int q0 = blockIdx.x * 128;
    const __half* Qp = g_Qh + (size_t)bh*SEQ*HD;
    const __half* Kp = g_Kh + (size_t)bh*SEQ*HD;
    const __half* Vp = g_Vh + (size_t)bh*SEQ*HD;
    const int* mrow_g = mask + (size_t)b*SEQ;
    int row0 = w*16 + g;

    // per-thread K/V tile load slots: 64 rows x 8 chunks(16B), 2 per thread
    int ldr0 = tid >> 3, ldc = tid & 7;
    int ldr1 = ldr0 + 32;
    uint32_t so0 = (ldr0*STR + ldc*8)*2;   // smem byte offsets
    uint32_t so1 = (ldr1*STR + ldc*8)*2;
    size_t   go0 = (size_t)ldr0*HD + ldc*8;
    size_t   go1 = (size_t)ldr1*HD + ldc*8;

    // ---- Q tile (sync) + mask row (sync) ----
    #pragma unroll
    for (int j = 0; j < 4; j++){
        int lin = tid + j*256;
        int row = lin >> 3, ch = lin & 7;
        uint4 v = *reinterpret_cast<const uint4*>(Qp + (size_t)(q0+row)*HD + ch*8);
        *reinterpret_cast<uint4*>(smc + SM_QH + row*(STR*2) + ch*16) = v;
    }
    #pragma unroll
    for (int j = 0; j < 2; j++){
        int lin = tid + j*256;
        int4 v = *reinterpret_cast<const int4*>(mrow_g + lin*4);
        *reinterpret_cast<int4*>(Msk + lin*4) = v;
    }

    // ---- prologue: K(0), K(1) ----
    cp16(kbuf[0] + so0, Kp + go0);
    cp16(kbuf[0] + so1, Kp + go1);
    CP_COMMIT();
    cp16(kbuf[1] + so0, Kp + 64*HD + go0);
    cp16(kbuf[1] + so1, Kp + 64*HD + go1);
    CP_COMMIT();

    // ---------------- PASS 1: rowsum of ex2(QK) ----------------
    float lsum0 = 0.f, lsum1 = 0.f;
    int cur = 0, pf = 2;
    for (int kt = 0; kt < 32; kt++){
        if (kt == 31) { CP_WAIT0(); } else { CP_WAIT1(); }
        __syncthreads();
        if (kt < 30){
            const __half* src = Kp + (size_t)(kt+2)*64*HD;
            cp16(kbuf[pf] + so0, src + go0);
            cp16(kbuf[pf] + so1, src + go1);
            CP_COMMIT();
        }
        uint32_t kba = kbuf[cur];
        int kb0 = kt*64;

        float c[8][4];
        #pragma unroll
        for (int ni=0; ni<8; ni++){ c[ni][0]=0.f; c[ni][1]=0.f; c[ni][2]=0.f; c[ni][3]=0.f; }
        #pragma unroll
        for (int k16 = 0; k16 < 4; k16++){
            uint32_t a[4];
            ldsm4(a, qb + ((w*16+lrow16)*STR + k16*16 + lchunk)*2);
            uint32_t bq[4][4];
            #pragma unroll
            for (int nq=0; nq<4; nq++)
                ldsm4(bq[nq], kba + ((nq*16+bnrow)*STR + k16*16 + lchunk)*2);
            #pragma unroll
            for (int nq=0; nq<4; nq++)
                #pragma unroll
                for (int sub=0; sub<2; sub++){
                    uint32_t bb[2] = { bq[nq][sub], bq[nq][sub+2] };
                    mma16(c[nq*2+sub], a, bb);
                }
        }
        #pragma unroll
        for (int ni=0; ni<8; ni++){
            int col = kb0 + ni*8 + 2*t;
            bool m0 = (Msk[col] == 0), m1 = (Msk[col+1] == 0);
            lsum0 += (m0?0.f:ex2f(c[ni][0])) + (m1?0.f:ex2f(c[ni][1]));
            lsum1 += (m0?0.f:ex2f(c[ni][2])) + (m1?0.f:ex2f(c[ni][3]));
        }
        cur = (cur==2) ? 0 : cur+1;
        pf  = (pf==2)  ? 0 : pf+1;
    }
    lsum0 += __shfl_xor_sync(0xffffffffu, lsum0, 1);
    lsum0 += __shfl_xor_sync(0xffffffffu, lsum0, 2);
    lsum1 += __shfl_xor_sync(0xffffffffu, lsum1, 1);
    lsum1 += __shfl_xor_sync(0xffffffffu, lsum1, 2);
    float il0 = 1.0f / lsum0;
    float il1 = 1.0f / lsum1;

    __syncthreads();   // all warps done with pass-1 buffers before reuse

    // ---------------- PASS 2: normalized P -> attn + PV ----------------
    float co[8][4];
    #pragma unroll
    for (int ni=0; ni<8; ni++){ co[ni][0]=0.f; co[ni][1]=0.f; co[ni][2]=0.f; co[ni][3]=0.f; }

    // prologue: KV(0), KV(1)
    cp16(kbuf[0] + so0, Kp + go0);
    cp16(kbuf[0] + so1, Kp + go1);
    cp16(vbuf[0] + so0, Vp + go0);
    cp16(vbuf[0] + so1, Vp + go1);
    CP_COMMIT();
    cp16(kbuf[1] + so0, Kp + 64*HD + go0);
    cp16(kbuf[1] + so1, Kp + 64*HD + go1);
    cp16(vbuf[1] + so0, Vp + 64*HD + go0);
    cp16(vbuf[1] + so1, Vp + 64*HD + go1);
    CP_COMMIT();

    float* ar0 = attn + ((size_t)bh*SEQ + q0 + row0)*SEQ;
    float* ar1 = ar0 + (size_t)8*SEQ;

    cur = 0; pf = 2;
    for (int kt = 0; kt < 32; kt++){
        if (kt == 31) { CP_WAIT0(); } else { CP_WAIT1(); }
        __syncthreads();
        if (kt < 30){
            const __half* ksrc = Kp + (size_t)(kt+2)*64*HD;
            const __half* vsrc = Vp + (size_t)(kt+2)*64*HD;
            cp16(kbuf[pf] + so0, ksrc + go0);
            cp16(kbuf[pf] + so1, ksrc + go1);
            cp16(vbuf[pf] + so0, vsrc + go0);
            cp16(vbuf[pf] + so1, vsrc + go1);
            CP_COMMIT();
        }
        uint32_t kba = kbuf[cur], vba = vbuf[cur];
        int kb0 = kt*64;

        // ---- QK ----
        float c[8][4];
        #pragma unroll
        for (int ni=0; ni<8; ni++){ c[ni][0]=0.f; c[ni][1]=0.f; c[ni][2]=0.f; c[ni][3]=0.f; }
        #pragma unroll
        for (int k16 = 0; k16 < 4; k16++){
            uint32_t a[4];
            ldsm4(a, qb + ((w*16+lrow16)*STR + k16*16 + lchunk)*2);
            uint32_t bq[4][4];
            #pragma unroll
            for (int nq=0; nq<4; nq++)
                ldsm4(bq[nq], kba + ((nq*16+bnrow)*STR + k16*16 + lchunk)*2);
            #pragma unroll
            for (int nq=0; nq<4; nq++)
                #pragma unroll
                for (int sub=0; sub<2; sub++){
                    uint32_t bb[2] = { bq[nq][sub], bq[nq][sub+2] };
                    mma16(c[nq*2+sub], a, bb);
                }
        }

        // ---- normalized P: streaming fp32 attn store + fp16 pack for PV ----
        uint32_t ph0[8], ph1[8];
        #pragma unroll
        for (int ni=0; ni<8; ni++){
            int cl = ni*8 + 2*t;
            int col = kb0 + cl;
            bool m0 = (Msk[col] == 0), m1 = (Msk[col+1] == 0);
            float p00 = m0 ? 0.f : ex2f(c[ni][0]) * il0;
            float p01 = m1 ? 0.f : ex2f(c[ni][1]) * il0;
            float p10 = m0 ? 0.f : ex2f(c[ni][2]) * il1;
            float p11 = m1 ? 0.f : ex2f(c[ni][3]) * il1;
            __stcs(reinterpret_cast<float2*>(ar0 + col), make_float2(p00, p01));
            __stcs(reinterpret_cast<float2*>(ar1 + col), make_float2(p10, p11));
            __half2 h0v = __floats2half2_rn(p00, p01);
            __half2 h1v = __floats2half2_rn(p10, p11);
            ph0[ni] = *(uint32_t*)&h0v;
            ph1[ni] = *(uint32_t*)&h1v;
        }

        // ---- PV: A-frags directly from registers ----
        #pragma unroll
        for (int k16 = 0; k16 < 4; k16++){
            uint32_t ap[4] = { ph0[2*k16], ph1[2*k16], ph0[2*k16+1], ph1[2*k16+1] };
            #pragma unroll
            for (int ni2 = 0; ni2 < 4; ni2++){
                uint32_t bv4[4];
                ldsm4t(bv4, vba + ((k16*16+lrow16)*STR + ni2*16 + lchunk)*2);
                mma16(co[ni2*2],   ap, bv4);
                mma16(co[ni2*2+1], ap, bv4+2);
            }
        }
        cur = (cur==2) ? 0 : cur+1;
        pf  = (pf==2)  ? 0 : pf+1;
    }

    // ---- write O (already normalized) to g_Oh[b, q, h*64+d] ----
    __half* Op = g_Oh + ((size_t)b*SEQ + q0 + w*16)*EMBED + h*HD;
    #pragma unroll
    for (int ni=0; ni<8; ni++){
        int cl = ni*8 + 2*t;
        __half2 o0 = __floats2half2_rn(co[ni][0], co[ni][1]);
        __half2 o1 = __floats2half2_rn(co[ni][2], co[ni][3]);
        *reinterpret_cast<__half2*>(Op + (size_t)g*EMBED + cl)     = o0;
        *reinterpret_cast<__half2*>(Op + (size_t)(g+8)*EMBED + cl) = o1;
    }
}

// ============================================================================
// Kernel 3: out = g_Oh @ Wo.T + bo   (M=8192, N=512, K=512)  fp16 MMA
// ============================================================================
#define OP_SMEM_BYTES (128*STR*2 + 64*STR*2)

__global__ __launch_bounds__(256)
void oproj_kernel(const float* __restrict__ Wo, const float* __restrict__ bo,
                  float* __restrict__ out){
    extern __shared__ char osmc[];
    uint32_t ab = saddr(osmc);
    uint32_t bb_ = saddr(osmc + 128*STR*2);
    __half* Bh = (__half*)(osmc + 128*STR*2);

    int tid = threadIdx.x, lane = tid & 31, warp = tid >> 5;
    int wm = warp >> 1, wn = warp & 1, rm = wm*32;
    int g = lane >> 2, t = lane & 3;
    int lrow16 = lane & 15;
    int lchunk = (lane >> 4) << 3;
    int bnrow  = (lane & 7) + ((lane >> 3) & 1) * 8;
    int n0 = blockIdx.x * 64;
    int m0 = blockIdx.y * 128;

    float c[2][4][4];
    #pragma unroll
    for (int mi=0;mi<2;mi++)
        #pragma unroll
        for (int ni=0;ni<4;ni++)
            { c[mi][ni][0]=0.f;c[mi][ni][1]=0.f;c[mi][ni][2]=0.f;c[mi][ni][3]=0.f; }

    const __half* Ap = g_Oh + (size_t)m0*EMBED;

    for (int k0 = 0; k0 < 512; k0 += 64){
        __syncthreads();
        #pragma unroll
        for (int j = 0; j < 4; j++){
            int lin = tid + j*256;
            int row = lin >> 3, ch = lin & 7;
            uint4 v = *reinterpret_cast<const uint4*>(Ap + (size_t)row*EMBED + k0 + ch*8);
            *reinterpret_cast<uint4*>(osmc + row*(STR*2) + ch*16) = v;
        }
        #pragma unroll
        for (int j = 0; j < 2; j++){
            int lin = tid + j*256;
            int row = lin >> 3, c8 = (lin & 7) * 8;
            const float* src = Wo + (size_t)(n0+row)*512 + k0 + c8;
            float4 v0 = *reinterpret_cast<const float4*>(src);
            float4 v1 = *reinterpret_cast<const float4*>(src + 4);
            __half2 h0 = __floats2half2_rn(v0.x, v0.y);
            __half2 h1 = __floats2half2_rn(v0.z, v0.w);
            __half2 h2 = __floats2half2_rn(v1.x, v1.y);
            __half2 h3 = __floats2half2_rn(v1.z, v1.w);
            uint4 u; u.x = *(uint32_t*)&h0; u.y = *(uint32_t*)&h1;
            u.z = *(uint32_t*)&h2; u.w = *(uint32_t*)&h3;
            *reinterpret_cast<uint4*>((char*)Bh + row*(STR*2) + c8*2) = u;
        }
        __syncthreads();

        #pragma unroll
        for (int k16 = 0; k16 < 4; k16++){
            uint32_t a[2][4];
            #pragma unroll
            for (int mi=0; mi<2; mi++)
                ldsm4(a[mi], ab + ((rm+mi*16+lrow16)*STR + k16*16 + lchunk)*2);
            uint32_t bq[2][4];
            #pragma unroll
            for (int pr=0; pr<2; pr++)
                ldsm4(bq[pr], bb_ + ((wn*32+pr*16+bnrow)*STR + k16*16 + lchunk)*2);
            #pragma unroll
            for (int mi=0; mi<2; mi++)
                #pragma unroll
                for (int pr=0; pr<2; pr++)
                    #pragma unroll
                    for (int sub=0; sub<2; sub++){
                        uint32_t bb2[2] = { bq[pr][sub], bq[pr][sub+2] };
                        mma16(c[mi][pr*2+sub], a[mi], bb2);
                    }
        }
    }
    #pragma unroll
    for (int mi=0;mi<2;mi++)
        #pragma unroll
        for (int half=0; half<2; half++){
            int row = rm + mi*16 + half*8 + g;
            #pragma unroll
            for (int ni=0; ni<4; ni++){
                int col = wn*32 + ni*8 + 2*t;
                float2 bv = *reinterpret_cast<const float2*>(bo + n0 + col);
                *reinterpret_cast<float2*>(out + (size_t)(m0+row)*512 + n0 + col) =
                    make_float2(c[mi][ni][half*2] + bv.x, c[mi][ni][half*2+1] + bv.y);
            }
        }
}

// ============================================================================
// launch
// ============================================================================
extern "C" void kernel_launch(void* const* d_in, const int* in_sizes, int n_in,
                              void* d_out, int out_size){
    (void)in_sizes; (void)n_in; (void)out_size;
    const float* values = (const float*)d_in[0];
    const float* keys   = (const float*)d_in[1];
    const float* query  = (const float*)d_in[2];
    const int*   mask   = (const int*)d_in[3];
    const float* Wv     = (const float*)d_in[4];
    const float* Wk     = (const float*)d_in[5];
    const float* Wq     = (const float*)d_in[6];
    const float* Wo     = (const float*)d_in[7];
    const float* bo     = (const float*)d_in[8];

    float* out  = (float*)d_out;                              // [B,S,E]
    float* attn = out + (size_t)BATCH*SEQ*EMBED;              // [B,H,S,S]

    __half *qptr, *kptr, *vptr;
    cudaGetSymbolAddress((void**)&qptr, g_Qh);
    cudaGetSymbolAddress((void**)&kptr, g_Kh);
    cudaGetSymbolAddress((void**)&vptr, g_Vh);

    cudaFuncSetAttribute(attn_kernel, cudaFuncAttributeMaxDynamicSharedMemorySize,
                         SM_TOTAL);
    cudaFuncSetAttribute(oproj_kernel, cudaFuncAttributeMaxDynamicSharedMemorySize,
                         OP_SMEM_BYTES);
    cudaFuncSetAttribute(proj_kernel, cudaFuncAttributeMaxDynamicSharedMemorySize,
                         PJ_TOTAL);

    proj_kernel<<<dim3(SEQ/128, BATCH*NHEADS, 3), 256, PJ_TOTAL>>>(
        query, keys, values, Wq, Wk, Wv, qptr, kptr, vptr);

    attn_kernel<<<dim3(SEQ/128, BATCH*NHEADS), 256, SM_TOTAL>>>(mask, attn);

    oproj_kernel<<<dim3(EMBED/64, (BATCH*SEQ)/128), 256, OP_SMEM_BYTES>>>(Wo, bo, out);
}

// round 13
// speedup vs baseline: 1.3164x; 1.0239x over previous
#include <cuda_runtime.h>
#include <cuda_fp16.h>
#include <cstdint>

#define NHEADS 8
#define EMBED  512
#define HD     64
#define BATCH  4
#define SEQ    2048
#define STR    72   // smem tile stride in halves (144B rows)

// ---- scratch (allocation-free: __device__ globals) ----
__device__ __half g_Qh[BATCH*NHEADS*SEQ*HD];   // pre-scaled by log2(e)/sqrt(512)
__device__ __half g_Kh[BATCH*NHEADS*SEQ*HD];
__device__ __half g_Vh[BATCH*NHEADS*SEQ*HD];
__device__ __half g_Oh[BATCH*SEQ*EMBED];       // attention output pre-Wo (fp16)

__device__ __forceinline__ uint32_t saddr(const void* p){
    return (uint32_t)__cvta_generic_to_shared(p);
}
__device__ __forceinline__ void cp16(uint32_t d, const void* s){
    asm volatile("cp.async.cg.shared.global [%0], [%1], 16;\n" :: "r"(d), "l"(s));
}
#define CP_COMMIT() asm volatile("cp.async.commit_group;\n")
#define CP_WAIT0()  asm volatile("cp.async.wait_group 0;\n")
#define CP_WAIT1()  asm volatile("cp.async.wait_group 1;\n")

__device__ __forceinline__ void ldsm4(uint32_t* r, uint32_t a){
    asm volatile("ldmatrix.sync.aligned.m8n8.x4.shared.b16 {%0,%1,%2,%3}, [%4];\n"
        : "=r"(r[0]),"=r"(r[1]),"=r"(r[2]),"=r"(r[3]) : "r"(a));
}
__device__ __forceinline__ void ldsm4t(uint32_t* r, uint32_t a){
    asm volatile("ldmatrix.sync.aligned.m8n8.x4.trans.shared.b16 {%0,%1,%2,%3}, [%4];\n"
        : "=r"(r[0]),"=r"(r[1]),"=r"(r[2]),"=r"(r[3]) : "r"(a));
}
__device__ __forceinline__ void mma16(float* c, const uint32_t* a, const uint32_t* b){
    asm volatile(
        "mma.sync.aligned.m16n8k16.row.col.f32.f16.f16.f32 "
        "{%0,%1,%2,%3}, {%4,%5,%6,%7}, {%8,%9}, {%0,%1,%2,%3};\n"
        : "+f"(c[0]),"+f"(c[1]),"+f"(c[2]),"+f"(c[3])
        : "r"(a[0]),"r"(a[1]),"r"(a[2]),"r"(a[3]),"r"(b[0]),"r"(b[1]));
}
__device__ __forceinline__ float ex2f(float x){
    float y; asm("ex2.approx.f32 %0, %1;" : "=f"(y) : "f"(x)); return y;
}

// ============================================================================
// Kernel 1: fused QKV per-head projection via fp16 MMA.
// CTA = 128 seq rows x one (b,h) x one of Q/K/V (z). 8 warps x 16 rows.
// Q output pre-scaled by log2(e)/sqrt(512).
// ============================================================================
#define PJ_X  0                      // 128 x STR halves
#define PJ_W  18432                  // 64 x STR halves
#define PJ_TOTAL (18432 + 9216)

__global__ __launch_bounds__(256)
void proj_kernel(const float* __restrict__ Xq, const float* __restrict__ Xk,
                 const float* __restrict__ Xv,
                 const float* __restrict__ Wq, const float* __restrict__ Wk,
                 const float* __restrict__ Wv,
                 __half* __restrict__ Yq, __half* __restrict__ Yk,
                 __half* __restrict__ Yv){
    extern __shared__ char psm[];
    uint32_t xb = saddr(psm + PJ_X);
    uint32_t wb = saddr(psm + PJ_W);

    int z = blockIdx.z;
    const float* X = (z==0) ? Xq : (z==1) ? Xk : Xv;
    const float* W = (z==0) ? Wq : (z==1) ? Wk : Wv;
    __half*      Y = (z==0) ? Yq : (z==1) ? Yk : Yv;
    float sc = (z==0) ? 0.06375881311003162f : 1.0f;   // log2(e)/sqrt(512)

    int tid = threadIdx.x, lane = tid & 31, w = tid >> 5;
    int g = lane >> 2, t = lane & 3;
    int lrow16 = lane & 15;
    int lchunk = (lane >> 4) << 3;
    int bnrow  = (lane & 7) + ((lane >> 3) & 1) * 8;
    int bh = blockIdx.y; int b = bh >> 3; int h = bh & 7;
    int s0 = blockIdx.x * 128;

    #pragma unroll
    for (int j = 0; j < 8; j++){
        int lin = tid + j*256;
        int row = lin >> 4, c4 = (lin & 15) << 2;
        float4 v = *reinterpret_cast<const float4*>(
            X + (((size_t)b*SEQ + s0 + row)*NHEADS + h)*HD + c4);
        __half2 h0 = __floats2half2_rn(v.x, v.y);
        __half2 h1 = __floats2half2_rn(v.z, v.w);
        uint2 u; u.x = *(uint32_t*)&h0; u.y = *(uint32_t*)&h1;
        *reinterpret_cast<uint2*>(psm + PJ_X + (row*STR + c4)*2) = u;
    }
    #pragma unroll
    for (int j = 0; j < 4; j++){
        int lin = tid + j*256;
        int row = lin >> 4, c4 = (lin & 15) << 2;
        float4 v = *reinterpret_cast<const float4*>(W + (size_t)row*64 + c4);
        __half2 h0 = __floats2half2_rn(v.x, v.y);
        __half2 h1 = __floats2half2_rn(v.z, v.w);
        uint2 u; u.x = *(uint32_t*)&h0; u.y = *(uint32_t*)&h1;
        *reinterpret_cast<uint2*>(psm + PJ_W + (row*STR + c4)*2) = u;
    }
    __syncthreads();

    float c[8][4];
    #pragma unroll
    for (int ni=0; ni<8; ni++){ c[ni][0]=0.f; c[ni][1]=0.f; c[ni][2]=0.f; c[ni][3]=0.f; }
    #pragma unroll
    for (int k16 = 0; k16 < 4; k16++){
        uint32_t a[4];
        ldsm4(a, xb + ((w*16+lrow16)*STR + k16*16 + lchunk)*2);
        uint32_t bq[4][4];
        #pragma unroll
        for (int nq=0; nq<4; nq++)
            ldsm4(bq[nq], wb + ((nq*16+bnrow)*STR + k16*16 + lchunk)*2);
        #pragma unroll
        for (int nq=0; nq<4; nq++)
            #pragma unroll
            for (int sub=0; sub<2; sub++){
                uint32_t bb[2] = { bq[nq][sub], bq[nq][sub+2] };
                mma16(c[nq*2+sub], a, bb);
            }
    }

    __half* Yp = Y + ((size_t)bh*SEQ + s0 + w*16)*HD;
    #pragma unroll
    for (int ni=0; ni<8; ni++){
        int cl = ni*8 + 2*t;
        __half2 o0 = __floats2half2_rn(c[ni][0]*sc, c[ni][1]*sc);
        __half2 o1 = __floats2half2_rn(c[ni][2]*sc, c[ni][3]*sc);
        *reinterpret_cast<__half2*>(Yp + (size_t)g*HD + cl)     = o0;
        *reinterpret_cast<__half2*>(Yp + (size_t)(g+8)*HD + cl) = o1;
    }
}

// ============================================================================
// Kernel 2: two-pass fused attention, 8 warps x 16 q-rows, 3-stage cp.async
// ring. Q fragments hoisted out of the k-loops (register-resident),
// 4-way lsum accumulators, int2 mask loads.
// grid (16, 32), 256 threads, 81920 B smem -> 2 CTAs/SM.
// ============================================================================
#define SM_QH   0
#define SM_K0   18432
#define SM_V0   46080
#define SM_MSK  73728
#define SM_TOTAL 81920
#define KBUF    9216

__global__ __launch_bounds__(256, 2)
void attn_kernel(const int* __restrict__ mask, float* __restrict__ attn){
    extern __shared__ char smc[];
    int* Msk = (int*)(smc + SM_MSK);
    uint32_t qb = saddr(smc + SM_QH);
    uint32_t kbuf[3] = { saddr(smc + SM_K0), saddr(smc + SM_K0 + KBUF),
                         saddr(smc + SM_K0 + 2*KBUF) };
    uint32_t vbuf[3] = { saddr(smc + SM_V0), saddr(smc + SM_V0 + KBUF),
                         saddr(smc + SM_V0 + 2*KBUF) };

    int tid = threadIdx.x, lane = tid & 31, w = tid >> 5;
    int g = lane >> 2, t = lane & 3;
    int lrow16 = lane & 15;
    int lchunk = (lane >> 4) << 3;
    int bnrow  = (lane & 7) + ((lane >> 3) & 1) * 8;
    int bh = blockIdx.y, b = bh >> 3, h = bh & 7;
    int q0 = blockIdx.x * 128;
    const __half* Qp = g_Qh + (size_t)bh*SEQ*HD;
    const __half* Kp = g_Kh + (size_t)bh*SEQ*HD;
    const __half* Vp = g_Vh + (size_t)bh*SEQ*HD;
    const int* mrow_g = mask + (size_t)b*SEQ;
    int row0 = w*16 + g;

    int ldr0 = tid >> 3, ldc = tid & 7;
    int ldr1 = ldr0 + 32;
    uint32_t so0 = (ldr0*STR + ldc*8)*2;
    uint32_t so1 = (ldr1*STR + ldc*8)*2;
    size_t   go0 = (size_t)ldr0*HD + ldc*8;
    size_t   go1 = (size_t)ldr1*HD + ldc*8;

    // ---- Q tile (sync) + mask row (sync) ----
    #pragma unroll
    for (int j = 0; j < 4; j++){
        int lin = tid + j*256;
        int row = lin >> 3, ch = lin & 7;
        uint4 v = *reinterpret_cast<const uint4*>(Qp + (size_t)(q0+row)*HD + ch*8);
        *reinterpret_cast<uint4*>(smc + SM_QH + row*(STR*2) + ch*16) = v;
    }
    #pragma unroll
    for (int j = 0; j < 2; j++){
        int lin = tid + j*256;
        int4 v = *reinterpret_cast<const int4*>(mrow_g + lin*4);
        *reinterpret_cast<int4*>(Msk + lin*4) = v;
    }

    // prologue: K(0), K(1)
    cp16(kbuf[0] + so0, Kp + go0);
    cp16(kbuf[0] + so1, Kp + go1);
    CP_COMMIT();
    cp16(kbuf[1] + so0, Kp + 64*HD + go0);
    cp16(kbuf[1] + so1, Kp + 64*HD + go1);
    CP_COMMIT();

    __syncthreads();   // Q + mask visible to all warps

    // ---- hoisted Q fragments (invariant across all k tiles, both passes) ----
    uint32_t aq[4][4];
    #pragma unroll
    for (int k16 = 0; k16 < 4; k16++)
        ldsm4(aq[k16], qb + ((w*16+lrow16)*STR + k16*16 + lchunk)*2);

    // ---------------- PASS 1: rowsum of ex2(QK) ----------------
    float ls0a = 0.f, ls0b = 0.f, ls1a = 0.f, ls1b = 0.f;
    int cur = 0, pf = 2;
    for (int kt = 0; kt < 32; kt++){
        if (kt == 31) { CP_WAIT0(); } else { CP_WAIT1(); }
        __syncthreads();
        if (kt < 30){
            const __half* src = Kp + (size_t)(kt+2)*64*HD;
            cp16(kbuf[pf] + so0, src + go0);
            cp16(kbuf[pf] + so1, src + go1);
            CP_COMMIT();
        }
        uint32_t kba = kbuf[cur];
        int kb0 = kt*64;

        float c[8][4];
        #pragma unroll
        for (int ni=0; ni<8; ni++){ c[ni][0]=0.f; c[ni][1]=0.f; c[ni][2]=0.f; c[ni][3]=0.f; }
        #pragma unroll
        for (int k16 = 0; k16 < 4; k16++){
            uint32_t bq[4][4];
            #pragma unroll
            for (int nq=0; nq<4; nq++)
                ldsm4(bq[nq], kba + ((nq*16+bnrow)*STR + k16*16 + lchunk)*2);
            #pragma unroll
            for (int nq=0; nq<4; nq++)
                #pragma unroll
                for (int sub=0; sub<2; sub++){
                    uint32_t bb[2] = { bq[nq][sub], bq[nq][sub+2] };
                    mma16(c[nq*2+sub], aq[k16], bb);
                }
        }
        #pragma unroll
        for (int ni=0; ni<8; ni++){
            int col = kb0 + ni*8 + 2*t;
            int2 mm = *reinterpret_cast<const int2*>(Msk + col);
            bool m0 = (mm.x == 0), m1 = (mm.y == 0);
            if (ni & 1){
                ls0b += (m0?0.f:ex2f(c[ni][0])) + (m1?0.f:ex2f(c[ni][1]));
                ls1b += (m0?0.f:ex2f(c[ni][2])) + (m1?0.f:ex2f(c[ni][3]));
            } else {
                ls0a += (m0?0.f:ex2f(c[ni][0])) + (m1?0.f:ex2f(c[ni][1]));
                ls1a += (m0?0.f:ex2f(c[ni][2])) + (m1?0.f:ex2f(c[ni][3]));
            }
        }
        cur = (cur==2) ? 0 : cur+1;
        pf  = (pf==2)  ? 0 : pf+1;
    }
    float lsum0 = ls0a + ls0b, lsum1 = ls1a + ls1b;
    lsum0 += __shfl_xor_sync(0xffffffffu, lsum0, 1);
    lsum0 += __shfl_xor_sync(0xffffffffu, lsum0, 2);
    lsum1 += __shfl_xor_sync(0xffffffffu, lsum1, 1);
    lsum1 += __shfl_xor_sync(0xffffffffu, lsum1, 2);
    float il0 = 1.0f / lsum0;
    float il1 = 1.0f / lsum1;

    __syncthreads();   // all warps done with pass-1 buffers before reuse

    // ---------------- PASS 2: normalized P -> attn + PV ----------------
    float co[8][4];
    #pragma unroll
    for (int ni=0; ni<8; ni++){ co[ni][0]=0.f; co[ni][1]=0.f; co[ni][2]=0.f; co[ni][3]=0.f; }

    cp16(kbuf[0] + so0, Kp + go0);
    cp16(kbuf[0] + so1, Kp + go1);
    cp16(vbuf[0] + so0, Vp + go0);
    cp16(vbuf[0] + so1, Vp + go1);
    CP_COMMIT();
    cp16(kbuf[1] + so0, Kp + 64*HD + go0);
    cp16(kbuf[1] + so1, Kp + 64*HD + go1);
    cp16(vbuf[1] + so0, Vp + 64*HD + go0);
    cp16(vbuf[1] + so1, Vp + 64*HD + go1);
    CP_COMMIT();

    float* ar0 = attn + ((size_t)bh*SEQ + q0 + row0)*SEQ;
    float* ar1 = ar0 + (size_t)8*SEQ;

    cur = 0; pf = 2;
    for (int kt = 0; kt < 32; kt++){
        if (kt == 31) { CP_WAIT0(); } else { CP_WAIT1(); }
        __syncthreads();
        if (kt < 30){
            const __half* ksrc = Kp + (size_t)(kt+2)*64*HD;
            const __half* vsrc = Vp + (size_t)(kt+2)*64*HD;
            cp16(kbuf[pf] + so0, ksrc + go0);
            cp16(kbuf[pf] + so1, ksrc + go1);
            cp16(vbuf[pf] + so0, vsrc + go0);
            cp16(vbuf[pf] + so1, vsrc + go1);
            CP_COMMIT();
        }
        uint32_t kba = kbuf[cur], vba = vbuf[cur];
        int kb0 = kt*64;

        float c[8][4];
        #pragma unroll
        for (int ni=0; ni<8; ni++){ c[ni][0]=0.f; c[ni][1]=0.f; c[ni][2]=0.f; c[ni][3]=0.f; }
        #pragma unroll
        for (int k16 = 0; k16 < 4; k16++){
            uint32_t bq[4][4];
            #pragma unroll
            for (int nq=0; nq<4; nq++)
                ldsm4(bq[nq], kba + ((nq*16+bnrow)*STR + k16*16 + lchunk)*2);
            #pragma unroll
            for (int nq=0; nq<4; nq++)
                #pragma unroll
                for (int sub=0; sub<2; sub++){
                    uint32_t bb[2] = { bq[nq][sub], bq[nq][sub+2] };
                    mma16(c[nq*2+sub], aq[k16], bb);
                }
        }

        uint32_t ph0[8], ph1[8];
        #pragma unroll
        for (int ni=0; ni<8; ni++){
            int cl = ni*8 + 2*t;
            int col = kb0 + cl;
            int2 mm = *reinterpret_cast<const int2*>(Msk + col);
            bool m0 = (mm.x == 0), m1 = (mm.y == 0);
            float p00 = m0 ? 0.f : ex2f(c[ni][0]) * il0;
            float p01 = m1 ? 0.f : ex2f(c[ni][1]) * il0;
            float p10 = m0 ? 0.f : ex2f(c[ni][2]) * il1;
            float p11 = m1 ? 0.f : ex2f(c[ni][3]) * il1;
            __stcs(reinterpret_cast<float2*>(ar0 + col), make_float2(p00, p01));
            __stcs(reinterpret_cast<float2*>(ar1 + col), make_float2(p10, p11));
            __half2 h0v = __floats2half2_rn(p00, p01);
            __half2 h1v = __floats2half2_rn(p10, p11);
            ph0[ni] = *(uint32_t*)&h0v;
            ph1[ni] = *(uint32_t*)&h1v;
        }

        #pragma unroll
        for (int k16 = 0; k16 < 4; k16++){
            uint32_t ap[4] = { ph0[2*k16], ph1[2*k16], ph0[2*k16+1], ph1[2*k16+1] };
            #pragma unroll
            for (int ni2 = 0; ni2 < 4; ni2++){
                uint32_t bv4[4];
                ldsm4t(bv4, vba + ((k16*16+lrow16)*STR + ni2*16 + lchunk)*2);
                mma16(co[ni2*2],   ap, bv4);
                mma16(co[ni2*2+1], ap, bv4+2);
            }
        }
        cur = (cur==2) ? 0 : cur+1;
        pf  = (pf==2)  ? 0 : pf+1;
    }

    __half* Op = g_Oh + ((size_t)b*SEQ + q0 + w*16)*EMBED + h*HD;
    #pragma unroll
    for (int ni=0; ni<8; ni++){
        int cl = ni*8 + 2*t;
        __half2 o0 = __floats2half2_rn(co[ni][0], co[ni][1]);
        __half2 o1 = __floats2half2_rn(co[ni][2], co[ni][3]);
        *reinterpret_cast<__half2*>(Op + (size_t)g*EMBED + cl)     = o0;
        *reinterpret_cast<__half2*>(Op + (size_t)(g+8)*EMBED + cl) = o1;
    }
}

// ============================================================================
// Kernel 3: out = g_Oh @ Wo.T + bo   (M=8192, N=512, K=512)  fp16 MMA
// ============================================================================
#define OP_SMEM_BYTES (128*STR*2 + 64*STR*2)

__global__ __launch_bounds__(256)
void oproj_kernel(const float* __restrict__ Wo, const float* __restrict__ bo,
                  float* __restrict__ out){
    extern __shared__ char osmc[];
    uint32_t ab = saddr(osmc);
    uint32_t bb_ = saddr(osmc + 128*STR*2);
    __half* Bh = (__half*)(osmc + 128*STR*2);

    int tid = threadIdx.x, lane = tid & 31, warp = tid >> 5;
    int wm = warp >> 1, wn = warp & 1, rm = wm*32;
    int g = lane >> 2, t = lane & 3;
    int lrow16 = lane & 15;
    int lchunk = (lane >> 4) << 3;
    int bnrow  = (lane & 7) + ((lane >> 3) & 1) * 8;
    int n0 = blockIdx.x * 64;
    int m0 = blockIdx.y * 128;

    float c[2][4][4];
    #pragma unroll
    for (int mi=0;mi<2;mi++)
        #pragma unroll
        for (int ni=0;ni<4;ni++)
            { c[mi][ni][0]=0.f;c[mi][ni][1]=0.f;c[mi][ni][2]=0.f;c[mi][ni][3]=0.f; }

    const __half* Ap = g_Oh + (size_t)m0*EMBED;

    for (int k0 = 0; k0 < 512; k0 += 64){
        __syncthreads();
        #pragma unroll
        for (int j = 0; j < 4; j++){
            int lin = tid + j*256;
            int row = lin >> 3, ch = lin & 7;
            uint4 v = *reinterpret_cast<const uint4*>(Ap + (size_t)row*EMBED + k0 + ch*8);
            *reinterpret_cast<uint4*>(osmc + row*(STR*2) + ch*16) = v;
        }
        #pragma unroll
        for (int j = 0; j < 2; j++){
            int lin = tid + j*256;
            int row = lin >> 3, c8 = (lin & 7) * 8;
            const float* src = Wo + (size_t)(n0+row)*512 + k0 + c8;
            float4 v0 = *reinterpret_cast<const float4*>(src);
            float4 v1 = *reinterpret_cast<const float4*>(src + 4);
            __half2 h0 = __floats2half2_rn(v0.x, v0.y);
            __half2 h1 = __floats2half2_rn(v0.z, v0.w);
            __half2 h2 = __floats2half2_rn(v1.x, v1.y);
            __half2 h3 = __floats2half2_rn(v1.z, v1.w);
            uint4 u; u.x = *(uint32_t*)&h0; u.y = *(uint32_t*)&h1;
            u.z = *(uint32_t*)&h2; u.w = *(uint32_t*)&h3;
            *reinterpret_cast<uint4*>((char*)Bh + row*(STR*2) + c8*2) = u;
        }
        __syncthreads();

        #pragma unroll
        for (int k16 = 0; k16 < 4; k16++){
            uint32_t a[2][4];
            #pragma unroll
            for (int mi=0; mi<2; mi++)
                ldsm4(a[mi], ab + ((rm+mi*16+lrow16)*STR + k16*16 + lchunk)*2);
            uint32_t bq[2][4];
            #pragma unroll
            for (int pr=0; pr<2; pr++)
                ldsm4(bq[pr], bb_ + ((wn*32+pr*16+bnrow)*STR + k16*16 + lchunk)*2);
            #pragma unroll
            for (int mi=0; mi<2; mi++)
                #pragma unroll
                for (int pr=0; pr<2; pr++)
                    #pragma unroll
                    for (int sub=0; sub<2; sub++){
                        uint32_t bb2[2] = { bq[pr][sub], bq[pr][sub+2] };
                        mma16(c[mi][pr*2+sub], a[mi], bb2);
                    }
        }
    }
    #pragma unroll
    for (int mi=0;mi<2;mi++)
        #pragma unroll
        for (int half=0; half<2; half++){
            int row = rm + mi*16 + half*8 + g;
            #pragma unroll
            for (int ni=0; ni<4; ni++){
                int col = wn*32 + ni*8 + 2*t;
                float2 bv = *reinterpret_cast<const float2*>(bo + n0 + col);
                *reinterpret_cast<float2*>(out + (size_t)(m0+row)*512 + n0 + col) =
                    make_float2(c[mi][ni][half*2] + bv.x, c[mi][ni][half*2+1] + bv.y);
            }
        }
}

// ============================================================================
// launch
// ============================================================================
extern "C" void kernel_launch(void* const* d_in, const int* in_sizes, int n_in,
                              void* d_out, int out_size){
    (void)in_sizes; (void)n_in; (void)out_size;
    const float* values = (const float*)d_in[0];
    const float* keys   = (const float*)d_in[1];
    const float* query  = (const float*)d_in[2];
    const int*   mask   = (const int*)d_in[3];
    const float* Wv     = (const float*)d_in[4];
    const float* Wk     = (const float*)d_in[5];
    const float* Wq     = (const float*)d_in[6];
    const float* Wo     = (const float*)d_in[7];
    const float* bo     = (const float*)d_in[8];

    float* out  = (float*)d_out;                              // [B,S,E]
    float* attn = out + (size_t)BATCH*SEQ*EMBED;              // [B,H,S,S]

    __half *qptr, *kptr, *vptr;
    cudaGetSymbolAddress((void**)&qptr, g_Qh);
    cudaGetSymbolAddress((void**)&kptr, g_Kh);
    cudaGetSymbolAddress((void**)&vptr, g_Vh);

    cudaFuncSetAttribute(attn_kernel, cudaFuncAttributeMaxDynamicSharedMemorySize,
                         SM_TOTAL);
    cudaFuncSetAttribute(oproj_kernel, cudaFuncAttributeMaxDynamicSharedMemorySize,
                         OP_SMEM_BYTES);
    cudaFuncSetAttribute(proj_kernel, cudaFuncAttributeMaxDynamicSharedMemorySize,
                         PJ_TOTAL);

    proj_kernel<<<dim3(SEQ/128, BATCH*NHEADS, 3), 256, PJ_TOTAL>>>(
        query, keys, values, Wq, Wk, Wv, qptr, kptr, vptr);

    attn_kernel<<<dim3(SEQ/128, BATCH*NHEADS), 256, SM_TOTAL>>>(mask, attn);

    oproj_kernel<<<dim3(EMBED/64, (BATCH*SEQ)/128), 256, OP_SMEM_BYTES>>>(Wo, bo, out);
}